// round 1
// baseline (speedup 1.0000x reference)
#include <cuda_runtime.h>
#include <math.h>

// Problem constants
#define BSZ 32
#define CCH 128
#define HH  32
#define WW  32
#define HWP (HH*WW)            // 1024
#define LL  (CCH*HWP)          // 131072 per batch
#define NTOT (BSZ*LL)          // 4194304
#define MMH 5                  // Anderson history
#define LAMREG 1e-4f
#define TOLV 1e-5f
#define ALPHA_D 0.9f

// ---------------- device state (no runtime allocation allowed) ----------------
__device__ float g_Z[MMH][NTOT];      // X history
__device__ float g_F[MMH][NTOT];      // Fh history
__device__ float g_S[BSZ][MMH][MMH];  // Gram matrix (incrementally maintained, symmetric)
__device__ float g_alpha[BSZ][MMH];
__device__ float g_resden;
__device__ int   g_flag;              // converged flag
__device__ int   g_outslot;           // slot of last executed body
__device__ float g_Wt[CCH*9*CCH];     // transposed weights: [(ci*9 + ky*3 + kx)*128 + co]

// ---------------- small kernels ----------------

__global__ void prep_w(const float* __restrict__ W) {
    int i = blockIdx.x * blockDim.x + threadIdx.x;
    if (i >= CCH * CCH * 9) return;
    int co = i / (CCH * 9);
    int r  = i % (CCH * 9);
    int ci = r / 9;
    int t  = r % 9;
    g_Wt[(ci * 9 + t) * CCH + co] = W[i];
}

__global__ void init_state() {
    int t = threadIdx.x;
    if (t == 0) { g_flag = 0; g_outslot = 0; g_resden = 0.f; }
    for (int i = t; i < BSZ * MMH * MMH; i += blockDim.x) ((float*)g_S)[i] = 0.f;
    for (int i = t; i < BSZ * MMH; i += blockDim.x) ((float*)g_alpha)[i] = 0.f;
}

__global__ void fill_z0() {
    int i = blockIdx.x * blockDim.x + threadIdx.x;   // over NTOT/4
    const float v = 1.0f / 128.0f;
    ((float4*)g_Z[0])[i] = make_float4(v, v, v, v);
}

// xnew = sum_{j<n} alpha_j * F[j]  ->  Z[s]
__global__ void update_x(int s, int n) {
    if (g_flag) return;
    int i4 = blockIdx.x * blockDim.x + threadIdx.x;  // over NTOT/4
    int b = i4 / (LL / 4);
    float a[MMH];
#pragma unroll
    for (int j = 0; j < MMH; j++) a[j] = g_alpha[b][j];
    float4 acc = make_float4(0.f, 0.f, 0.f, 0.f);
    for (int j = 0; j < n; j++) {
        float4 f = ((const float4*)g_F[j])[i4];
        acc.x = fmaf(a[j], f.x, acc.x);
        acc.y = fmaf(a[j], f.y, acc.y);
        acc.z = fmaf(a[j], f.z, acc.z);
        acc.w = fmaf(a[j], f.w, acc.w);
    }
    ((float4*)g_Z[s])[i4] = acc;
}

// Solve the masked (m+1)x(m+1) system per batch; 32 threads, 1 block.
__global__ void solve_k(int k) {
    if (g_flag) return;
    int b = threadIdx.x;
    if (b >= BSZ) return;
    int n = k < MMH ? k : MMH;
    int s = k % MMH;
    float A[6][6], rv[6];
    A[0][0] = 0.f;
    for (int j = 0; j < MMH; j++) {
        float a = (j < n) ? 1.f : 0.f;
        A[0][j + 1] = a; A[j + 1][0] = a;
    }
    for (int i = 0; i < MMH; i++)
        for (int j = 0; j < MMH; j++) {
            float v;
            if (i < n && j < n) v = g_S[b][i][j] + ((i == j) ? LAMREG : 0.f);
            else                v = (i == j) ? 1.f : 0.f;
            A[i + 1][j + 1] = v;
        }
    for (int i = 0; i < 6; i++) rv[i] = 0.f;
    rv[0] = 1.f;
    // Gaussian elimination with partial pivoting
    for (int c = 0; c < 6; c++) {
        int p = c; float mx = fabsf(A[c][c]);
        for (int r = c + 1; r < 6; r++) { float t = fabsf(A[r][c]); if (t > mx) { mx = t; p = r; } }
        if (p != c) {
            for (int q = c; q < 6; q++) { float t = A[c][q]; A[c][q] = A[p][q]; A[p][q] = t; }
            float t = rv[c]; rv[c] = rv[p]; rv[p] = t;
        }
        float inv = 1.f / A[c][c];
        for (int r = c + 1; r < 6; r++) {
            float f = A[r][c] * inv;
            if (f != 0.f) {
                for (int q = c + 1; q < 6; q++) A[r][q] -= f * A[c][q];
                rv[r] -= f * rv[c];
            }
        }
    }
    float xs[6];
    for (int c = 5; c >= 0; c--) {
        float t = rv[c];
        for (int q = c + 1; q < 6; q++) t -= A[c][q] * xs[q];
        xs[c] = t / A[c][c];
    }
    for (int j = 0; j < MMH; j++) g_alpha[b][j] = (j < n) ? xs[j + 1] : 0.f;
    // zero Gram row/col s for the upcoming refill by the f-kernel epilogue
    for (int j = 0; j < MMH; j++) { g_S[b][s][j] = 0.f; g_S[b][j][s] = 0.f; }
}

__global__ void check_k(int k) {
    if (g_flag) return;
    int s = k % MMH;
    float rn = 0.f;
    for (int b = 0; b < BSZ; b++) rn += g_S[b][s][s];   // sum_b ||g_s||^2 = resnum
    float res = sqrtf(rn) / (1e-5f + sqrtf(g_resden));
    g_outslot = s;
    if (res < TOLV) g_flag = 1;
    g_resden = 0.f;
}

__global__ void final_copy(float* __restrict__ out) {
    int i4 = blockIdx.x * blockDim.x + threadIdx.x;  // over NTOT/4
    int sl = g_outslot;
    ((float4*)out)[i4] = ((const float4*)g_F[sl])[i4];
}

// ---------------- fused f-evaluation kernel ----------------
// Computes fnew = softmax_ch((1-a)*z + a*(Conv3x3(mask-inject(z)) + bias)),
// writes F[s] (and optionally Z[out2slot]), and in the epilogue incrementally
// updates Gram row/col s plus the residual denominator.
// Block = (y, b), 256 threads. Thread tile: 4 out-channels x 4 pixels.

#define SWID 36
#define SMEM_FLOATS (3 * CCH * SWID)
#define SMEM_BYTES (SMEM_FLOATS * 4)

__device__ __forceinline__ float warpReduceSum(float v) {
#pragma unroll
    for (int o = 16; o > 0; o >>= 1) v += __shfl_xor_sync(0xFFFFFFFF, v, o);
    return v;
}

__global__ void f_eval(int s, int out2slot, int nact, int do_res,
                       const float* __restrict__ xg, const int* __restrict__ maskg,
                       const float* __restrict__ bias) {
    if (g_flag) return;
    extern __shared__ float sm[];
    __shared__ float sMax[WW], sInv[WW], sW8[8];

    const int y = blockIdx.x;
    const int b = blockIdx.y;
    const int tid = threadIdx.x;
    const float* __restrict__ zin = g_Z[s];
    float* __restrict__ fout = g_F[s];
    float* __restrict__ out2 = (out2slot >= 0) ? g_Z[out2slot] : nullptr;

    // ---- stage masked input rows (y-1, y, y+1) into smem with 1-col halo ----
    for (int i = tid; i < 3 * CCH; i += 256) { sm[i * SWID + 0] = 0.f; sm[i * SWID + 33] = 0.f; }
    for (int i = tid; i < 3 * CCH * WW; i += 256) {
        int ky = i / (CCH * WW);
        int r  = i % (CCH * WW);
        int ci = r / WW;
        int x  = r % WW;
        int yy = y + ky - 1;
        float v = 0.f;
        if (yy >= 0 && yy < HH) {
            int zi = ((b * CCH + ci) * HH + yy) * WW + x;
            float z = zin[zi];
            int mf = maskg[(b * HH + yy) * WW + x];
            v = mf ? xg[zi] : z;
        }
        sm[(ky * CCH + ci) * SWID + x + 1] = v;
    }
    __syncthreads();

    // ---- conv 3x3: each thread does 4 co x 4 x ----
    const int x0 = (tid & 7) * 4;
    const int c0 = (tid >> 3) * 4;
    float acc[4][4];
#pragma unroll
    for (int c = 0; c < 4; c++)
#pragma unroll
        for (int xx = 0; xx < 4; xx++) acc[c][xx] = 0.f;

    for (int ci = 0; ci < CCH; ci++) {
#pragma unroll
        for (int ky = 0; ky < 3; ky++) {
            const float* zr = &sm[(ky * CCH + ci) * SWID + x0];
            float4 za = *(const float4*)zr;
            float2 zb = *(const float2*)(zr + 4);
            float zv[6] = { za.x, za.y, za.z, za.w, zb.x, zb.y };
            const float* wp = &g_Wt[(ci * 9 + ky * 3) * CCH + c0];
#pragma unroll
            for (int kx = 0; kx < 3; kx++) {
                float4 w = *(const float4*)(wp + kx * CCH);
                float wv[4] = { w.x, w.y, w.z, w.w };
#pragma unroll
                for (int c = 0; c < 4; c++)
#pragma unroll
                    for (int xx = 0; xx < 4; xx++)
                        acc[c][xx] = fmaf(wv[c], zv[xx + kx], acc[c][xx]);
            }
        }
    }

    // raw z for the damping term (pre = (1-a)*z + a*(lin+bias))
    float zq[4][4];
#pragma unroll
    for (int c = 0; c < 4; c++) {
        float4 t = *(const float4*)&zin[((b * CCH + c0 + c) * HH + y) * WW + x0];
        zq[c][0] = t.x; zq[c][1] = t.y; zq[c][2] = t.z; zq[c][3] = t.w;
    }
    float bi[4];
#pragma unroll
    for (int c = 0; c < 4; c++) bi[c] = bias[c0 + c];

    __syncthreads();          // done reading sm; reuse as pre[128][33]
    float* sPre = sm;
    const float c1 = 1.0f - ALPHA_D;
#pragma unroll
    for (int c = 0; c < 4; c++)
#pragma unroll
        for (int xx = 0; xx < 4; xx++)
            sPre[(c0 + c) * 33 + x0 + xx] = c1 * zq[c][xx] + ALPHA_D * (acc[c][xx] + bi[c]);
    __syncthreads();

    // ---- softmax stats per pixel (8 warps, 4 pixels each) ----
    {
        int w = tid >> 5, lane = tid & 31;
        for (int xx = w; xx < WW; xx += 8) {
            float m = -1e30f;
#pragma unroll
            for (int i = 0; i < 4; i++) m = fmaxf(m, sPre[(lane + 32 * i) * 33 + xx]);
#pragma unroll
            for (int o = 16; o > 0; o >>= 1) m = fmaxf(m, __shfl_xor_sync(0xFFFFFFFF, m, o));
            float ss = 0.f;
#pragma unroll
            for (int i = 0; i < 4; i++) ss += __expf(sPre[(lane + 32 * i) * 33 + xx] - m);
            ss = warpReduceSum(ss);
            if (lane == 0) { sMax[xx] = m; sInv[xx] = 1.0f / ss; }
        }
    }
    __syncthreads();

    // ---- output + fused Gram/residual epilogue ----
    const int x = tid & 31;
    const int cc0 = tid >> 5;
    float dots[MMH] = { 0.f, 0.f, 0.f, 0.f, 0.f };
    float resd = 0.f;
    for (int c = cc0; c < CCH; c += 8) {
        int idx = ((b * CCH + c) * HH + y) * WW + x;
        float val = __expf(sPre[c * 33 + x] - sMax[x]) * sInv[x];
        fout[idx] = val;
        if (out2) out2[idx] = val;
        float zi = zin[idx];
        float gs = val - zi;
#pragma unroll
        for (int j = 0; j < MMH; j++) {
            if (j < nact) {
                float gj = (j == s) ? gs : (g_F[j][idx] - g_Z[j][idx]);
                dots[j] = fmaf(gs, gj, dots[j]);
            }
        }
        resd = fmaf(val, val, resd);
    }

    // block-reduce the (<=6) scalars, then atomics
    int lane = tid & 31, w = tid >> 5;
#pragma unroll
    for (int j = 0; j < MMH; j++) {
        if (j >= nact) continue;
        float v = warpReduceSum(dots[j]);
        if (lane == 0) sW8[w] = v;
        __syncthreads();
        if (tid == 0) {
            float t = 0.f;
#pragma unroll
            for (int i = 0; i < 8; i++) t += sW8[i];
            atomicAdd(&g_S[b][s][j], t);
            if (j != s) atomicAdd(&g_S[b][j][s], t);
        }
        __syncthreads();
    }
    if (do_res) {
        float v = warpReduceSum(resd);
        if (lane == 0) sW8[w] = v;
        __syncthreads();
        if (tid == 0) {
            float t = 0.f;
#pragma unroll
            for (int i = 0; i < 8; i++) t += sW8[i];
            atomicAdd(&g_resden, t);
        }
    }
}

// ---------------- host orchestration (graph-capturable) ----------------
extern "C" void kernel_launch(void* const* d_in, const int* in_sizes, int n_in,
                              void* d_out, int out_size) {
    // robust input matching by element count
    const float* x = nullptr; const float* W = nullptr;
    const float* bias = nullptr; const int* mask = nullptr;
    for (int i = 0; i < n_in; i++) {
        switch (in_sizes[i]) {
            case 4194304: x    = (const float*)d_in[i]; break;
            case 147456:  W    = (const float*)d_in[i]; break;
            case 128:     bias = (const float*)d_in[i]; break;
            case 32768:   mask = (const int*)d_in[i];   break;
        }
    }
    float* out = (float*)d_out;

    cudaFuncSetAttribute(f_eval, cudaFuncAttributeMaxDynamicSharedMemorySize, SMEM_BYTES);

    dim3 fgrid(HH, BSZ);
    const int NB4 = NTOT / 4 / 256;   // 4096 blocks for elementwise float4 kernels

    prep_w<<<(CCH * CCH * 9 + 255) / 256, 256>>>(W);
    init_state<<<1, 256>>>();
    fill_z0<<<NB4, 256>>>();

    // F0 = f(z0); also Z[1] = F0.   (s=0, nact=1 -> fills S[0][0])
    f_eval<<<fgrid, 256, SMEM_BYTES>>>(0, 1, 1, 0, x, mask, bias);
    // F1 = f(F0).                   (s=1, nact=2 -> fills S[1][0..1])
    f_eval<<<fgrid, 256, SMEM_BYTES>>>(1, -1, 2, 0, x, mask, bias);

    for (int k = 2; k < 50; k++) {
        int s = k % MMH;
        int n = (k < MMH) ? k : MMH;
        int nactE = (k + 1 < MMH) ? (k + 1) : MMH;
        solve_k<<<1, 32>>>(k);
        update_x<<<NB4, 256>>>(s, n);
        f_eval<<<fgrid, 256, SMEM_BYTES>>>(s, -1, nactE, 1, x, mask, bias);
        check_k<<<1, 1>>>(k);
    }

    final_copy<<<NB4, 256>>>(out);
    (void)out_size;
}